// round 3
// baseline (speedup 1.0000x reference)
#include <cuda_runtime.h>

// Problem constants (fixed by the reference):
//   image 1000x1000, patch 5x5 -> 200x200 = 40000 patches
//   coefficients [40000, 3, 10, 2], bias [40000, 3]
//   out [3, 1000000]
#define IMG_W           1000
#define NUM_PIX         1000000
#define PATCH           5
#define PATCHES_PER_ROW 200
#define COEF_PER_PATCH  60          // 3*10*2
#define PB              40          // patches per block (one fifth of a patch-row)
#define NTHREADS        256         // 200 compute threads + spare for copies
#define SM_STRIDE       68          // 60 padded to 68 floats: conflict-free LDS.128

__global__ __launch_bounds__(NTHREADS, 5)
void ts_kernel(const float* __restrict__ pix,
               const float* __restrict__ coef,
               const float* __restrict__ bias,
               float* __restrict__ out)
{
    __shared__ float sc[PB * SM_STRIDE];            // 40*68*4   = 10880 B
    __shared__ float sb[PB * 3];                    //             480 B
    __shared__ float sp[PATCH * 2 * (PB * PATCH)];  // 5*400*4   =  8000 B (pixels)
    __shared__ float so[3 * PATCH * (PB * PATCH)];  // 3*5*200*4 = 12000 B (output)

    const int tid = threadIdx.x;
    const int b   = blockIdx.x;          // 0..999
    const int pr  = b / 5;               // patch row 0..199
    const int cb  = (b - pr * 5) * PB;   // patch-col base: 0,40,80,120,160
    const int pbase = pr * PATCHES_PER_ROW + cb;
    const int colBase = cb * PATCH;      // pixel column base (multiple of 200)

    // ---- Phase 1: cooperative loads (all fully coalesced float4) ----
    // Coefficients: 40 patches * 60 floats = 600 float4, contiguous in gmem.
    {
        const float4* g4 = (const float4*)(coef + (size_t)pbase * COEF_PER_PATCH);
        #pragma unroll
        for (int k = 0; k < 3; k++) {
            int idx = tid + k * NTHREADS;
            if (idx < 600) {
                float4 v = g4[idx];
                int pp  = idx / 15;        // 15 float4 per patch
                int off = idx - pp * 15;
                *(float4*)&sc[pp * SM_STRIDE + off * 4] = v;
            }
        }
        if (tid < PB * 3) sb[tid] = bias[(size_t)pbase * 3 + tid];

        // Pixels: 5 image rows x 200 px x 2 floats = 500 float4, each row contiguous.
        const float4* p4 = (const float4*)pix;
        #pragma unroll
        for (int k = 0; k < 2; k++) {
            int idx = tid + k * NTHREADS;
            if (idx < 500) {
                int r   = idx / 100;       // image row within block (0..4)
                int off = idx - r * 100;   // float4 within row
                int gf4 = ((pr * PATCH + r) * IMG_W + colBase) / 2 + off;
                *(float4*)&sp[r * 400 + off * 4] = p4[gf4];
            }
        }
    }
    __syncthreads();

    // ---- Phase 2: compute (200 threads; thread = 5-pixel segment of one patch) ----
    if (tid < PB * PATCH) {
        const int p_local = tid % PB;        // 0..39
        const int seg     = tid / PB;        // 0..4 (pixel row within patch)

        // Pixel coords from smem: 5 LDS.64, conflict-free (40B lane stride)
        float x[PATCH], y[PATCH];
        {
            const float* ps = &sp[seg * 400 + p_local * 10];
            #pragma unroll
            for (int i = 0; i < PATCH; i++) {
                float2 v = *(const float2*)&ps[2 * i];
                x[i] = v.x; y[i] = v.y;
            }
        }

        const float* cc0 = &sc[p_local * SM_STRIDE];

        #pragma unroll
        for (int ch = 0; ch < 3; ch++) {
            const float* cc = cc0 + ch * 20;   // [t*2+d], t=0..9, d in {x,y}
            const float bv = sb[p_local * 3 + ch];

            float rx[PATCH], ry[PATCH];
            {
                float4 v = *(const float4*)(cc + 16);   // (cx8, cy8, cx9, cy9)
                #pragma unroll
                for (int i = 0; i < PATCH; i++) {
                    rx[i] = fmaf(v.z, x[i], v.x);
                    ry[i] = fmaf(v.w, y[i], v.y);
                }
            }
            #pragma unroll
            for (int j = 3; j >= 0; j--) {
                float4 v = *(const float4*)(cc + j * 4);  // (cx_2j, cy_2j, cx_2j+1, cy_2j+1)
                #pragma unroll
                for (int i = 0; i < PATCH; i++) {
                    rx[i] = fmaf(rx[i], x[i], v.z);
                    ry[i] = fmaf(ry[i], y[i], v.w);
                }
                #pragma unroll
                for (int i = 0; i < PATCH; i++) {
                    rx[i] = fmaf(rx[i], x[i], v.x);
                    ry[i] = fmaf(ry[i], y[i], v.y);
                }
            }
            float* dst = &so[(ch * PATCH + seg) * (PB * PATCH) + p_local * PATCH];
            #pragma unroll
            for (int i = 0; i < PATCH; i++)
                dst[i] = rx[i] + ry[i] + bv;
        }
    }
    __syncthreads();

    // ---- Phase 3: coalesced float4 output copy ----
    {
        const float4* s4 = (const float4*)so;
        #pragma unroll
        for (int k = 0; k < 3; k++) {
            int j = tid + k * NTHREADS;
            if (j < 750) {
                int chseg = j / 50;           // 50 float4 per (ch,seg) row
                int off   = j - chseg * 50;
                int ch    = chseg / PATCH;
                int seg   = chseg - ch * PATCH;
                int gfl   = ch * NUM_PIX + (pr * PATCH + seg) * IMG_W + colBase + off * 4;
                *(float4*)&out[gfl] = s4[j];
            }
        }
    }
}

extern "C" void kernel_launch(void* const* d_in, const int* in_sizes, int n_in,
                              void* d_out, int out_size)
{
    const float* pix  = (const float*)d_in[0];   // [1000000, 2]
    const float* coef = (const float*)d_in[1];   // [40000, 3, 10, 2]
    const float* bias = (const float*)d_in[2];   // [40000, 3]
    float* out = (float*)d_out;                  // [3, 1000000]

    (void)in_sizes; (void)n_in; (void)out_size;
    ts_kernel<<<1000, NTHREADS>>>(pix, coef, bias, out);
}